// round 8
// baseline (speedup 1.0000x reference)
#include <cuda_runtime.h>
#include <cstdint>

// Problem constants (from reference setup_inputs)
#define BATCH 128
#define CHAN  2048
#define PSZ   14
#define HW    196              // 14*14
#define NBOX  36

#define CT      32             // channels per block tile
#define TS      197            // smem row stride (197 % 32 = 5 -> conflict-free patterns proven below)
#define NTHREADS 256

// Output layout: fc [B,C] | att [B,HW,C] | bu [B,R,C]
#define OFF_ATT ((size_t)BATCH * CHAN)                          // 262144
#define OFF_BU  (OFF_ATT + (size_t)BATCH * HW * CHAN)           // 51642368

__global__ __launch_bounds__(NTHREADS)
void fused_pool_transpose_kernel(const float* __restrict__ images,
                                 const float* __restrict__ boxes,
                                 float* __restrict__ out)
{
    const int b   = blockIdx.y;
    const int c0  = blockIdx.x * CT;
    const int tid = threadIdx.x;

    __shared__ float tile[CT * TS];
    __shared__ int   bx1[NBOX], by1[NBOX], bx2[NBOX], by2[NBOX];
    __shared__ float binv[NBOX];

    // ---- Phase 0: box coords (threads 0..35) ----
    if (tid < NBOX) {
        const float* bp = boxes + ((size_t)b * NBOX + tid) * 4;
        int x1 = (int)rintf(bp[0] * (float)PSZ);
        int y1 = (int)rintf(bp[1] * (float)PSZ);
        int x2 = (int)rintf(bp[2] * (float)PSZ);
        int y2 = (int)rintf(bp[3] * (float)PSZ);
        // degenerate-box fix (matches reference exactly)
        if (x1 == x2) {
            if (x2 < PSZ)      x2 += 1;
            else if (x1 > 0)   x1 -= 1;
        }
        if (y1 == y2) {
            if (y2 < PSZ)      y2 += 1;
            else if (y1 > 0)   y1 -= 1;
        }
        bx1[tid] = x1; by1[tid] = y1; bx2[tid] = x2; by2[tid] = y2;
        binv[tid] = 1.0f / (float)((y2 - y1) * (x2 - x1));
    }

    // ---- Phase 1: coalesced tile load (scalar LDG, conflict-free STS) ----
    // Incremental (c,p) indexing: i += 256 -> c += 1, p += 60, wrap once if needed.
    {
        const float* src = images + ((size_t)b * CHAN + c0) * HW;
        int c = tid / HW;              // 0 or 1
        int p = tid - c * HW;
        #pragma unroll 5
        for (int i = tid; i < CT * HW; i += NTHREADS) {
            tile[c * TS + p] = src[i];
            p += NTHREADS - HW;        // +60
            c += 1;
            if (p >= HW) { p -= HW; c += 1; }
        }
    }
    __syncthreads();

    // ---- Phase 2: att transpose, vectorized STG.128 ----
    // lane = psub*8 + cg: lane covers channels 4*cg..4*cg+3 at position p0+psub.
    // LDS banks: (4*cg+k)*197 + p  ->  (20*cg + 5*k + p) mod 32: all 32 lanes
    // distinct per k-step (20*cg spans the 8 multiples of 4; psub adds 0..3).
    {
        const int wid  = tid >> 5;
        const int lane = tid & 31;
        const int psub = lane >> 3;        // 0..3
        const int cg   = lane & 7;         // 0..7 -> channels 4*cg..4*cg+3
        const float* t0 = tile + (4 * cg + 0) * TS;
        const float* t1 = tile + (4 * cg + 1) * TS;
        const float* t2 = tile + (4 * cg + 2) * TS;
        const float* t3 = tile + (4 * cg + 3) * TS;
        float* attb = out + OFF_ATT + (size_t)b * HW * CHAN + c0 + 4 * cg;
        // p0 takes values wid*4 + 32m; max generated p0 = 192 -> p <= 195, no guard needed
        for (int p0 = wid * 4; p0 < HW; p0 += 32) {
            const int p = p0 + psub;
            float4 v;
            v.x = t0[p];
            v.y = t1[p];
            v.z = t2[p];
            v.w = t3[p];
            *reinterpret_cast<float4*>(attb + (size_t)p * CHAN) = v;
        }
    }
    __syncthreads();

    // ---- Phase 3a: in-place y-prefix per (channel, x) column ----
    // After this, tile[c][y][x] = sum_{y'<=y} images[c][y'][x].
    for (int t = tid; t < CT * PSZ; t += NTHREADS) {
        const int c = t / PSZ;
        const int x = t - c * PSZ;
        float* col = tile + c * TS + x;
        float s = col[0];
        #pragma unroll
        for (int y = 1; y < PSZ; ++y) {
            s += col[y * PSZ];
            col[y * PSZ] = s;
        }
    }
    __syncthreads();

    // ---- Phase 3b: bu box means + fc (task 36 == full-plane mean) ----
    // Warp-uniform r (t>>5), lanes = channels -> LDS stride 197 = conflict-free.
    for (int t = tid; t < 37 * 32; t += NTHREADS) {
        const int r = t >> 5;
        const int c = t & 31;
        const float* tp = tile + c * TS;
        if (r < NBOX) {
            const int x1 = bx1[r], x2 = bx2[r];
            const int y1 = by1[r], y2 = by2[r];
            const float* bot = tp + (y2 - 1) * PSZ;
            float s = 0.0f;
            if (y1 > 0) {
                const float* top = tp + (y1 - 1) * PSZ;
                for (int x = x1; x < x2; ++x) s += bot[x] - top[x];
            } else {
                for (int x = x1; x < x2; ++x) s += bot[x];
            }
            out[OFF_BU + ((size_t)b * NBOX + r) * CHAN + c0 + c] = s * binv[r];
        } else {
            // fc: total = sum of last prefix row
            const float* last = tp + (PSZ - 1) * PSZ;
            float s = 0.0f;
            #pragma unroll
            for (int x = 0; x < PSZ; ++x) s += last[x];
            out[(size_t)b * CHAN + c0 + c] = s * (1.0f / (float)HW);
        }
    }
}

extern "C" void kernel_launch(void* const* d_in, const int* in_sizes, int n_in,
                              void* d_out, int out_size)
{
    const float* images = (const float*)d_in[0];
    const float* boxes  = (const float*)d_in[1];
    float* out = (float*)d_out;

    dim3 grid(CHAN / CT, BATCH);   // (64, 128) = 8192 blocks
    fused_pool_transpose_kernel<<<grid, NTHREADS>>>(images, boxes, out);
}

// round 9
// speedup vs baseline: 1.1462x; 1.1462x over previous
#include <cuda_runtime.h>
#include <cstdint>

// Problem constants (from reference setup_inputs)
#define BATCH 128
#define CHAN  2048
#define PSZ   14
#define HW    196              // 14*14
#define NBOX  36

#define CT      32             // channels per block tile
#define TS      197            // smem row stride (197 % 32 = 5 -> conflict-free patterns proven below)
#define NTHREADS 256

// Output layout: fc [B,C] | att [B,HW,C] | bu [B,R,C]
#define OFF_ATT ((size_t)BATCH * CHAN)                          // 262144
#define OFF_BU  (OFF_ATT + (size_t)BATCH * HW * CHAN)           // 51642368

__global__ __launch_bounds__(NTHREADS)
void fused_pool_transpose_kernel(const float* __restrict__ images,
                                 const float* __restrict__ boxes,
                                 float* __restrict__ out)
{
    const int b   = blockIdx.y;
    const int c0  = blockIdx.x * CT;
    const int tid = threadIdx.x;

    __shared__ float tile[CT * TS];
    __shared__ int   bx1[NBOX], by1[NBOX], bx2[NBOX], by2[NBOX];
    __shared__ float binv[NBOX];

    // ---- Phase 0: box coords (threads 0..35) ----
    if (tid < NBOX) {
        const float* bp = boxes + ((size_t)b * NBOX + tid) * 4;
        int x1 = (int)rintf(bp[0] * (float)PSZ);
        int y1 = (int)rintf(bp[1] * (float)PSZ);
        int x2 = (int)rintf(bp[2] * (float)PSZ);
        int y2 = (int)rintf(bp[3] * (float)PSZ);
        // degenerate-box fix (matches reference exactly)
        if (x1 == x2) {
            if (x2 < PSZ)      x2 += 1;
            else if (x1 > 0)   x1 -= 1;
        }
        if (y1 == y2) {
            if (y2 < PSZ)      y2 += 1;
            else if (y1 > 0)   y1 -= 1;
        }
        bx1[tid] = x1; by1[tid] = y1; bx2[tid] = x2; by2[tid] = y2;
        binv[tid] = 1.0f / (float)((y2 - y1) * (x2 - x1));
    }

    // ---- Phase 1: coalesced tile load (scalar LDG, conflict-free STS) ----
    // Incremental (c,p) indexing: i += 256 -> c += 1, p += 60, wrap once if needed.
    {
        const float* src = images + ((size_t)b * CHAN + c0) * HW;
        int c = tid / HW;              // 0 or 1
        int p = tid - c * HW;
        #pragma unroll 5
        for (int i = tid; i < CT * HW; i += NTHREADS) {
            tile[c * TS + p] = src[i];
            p += NTHREADS - HW;        // +60
            c += 1;
            if (p >= HW) { p -= HW; c += 1; }
        }
    }
    __syncthreads();

    // ---- Phase 2: att transpose, vectorized STG.128 ----
    // lane = psub*8 + cg: lane covers channels 4*cg..4*cg+3 at position p0+psub.
    // LDS banks: (4*cg+k)*197 + p  ->  (20*cg + 5*k + p) mod 32: all 32 lanes
    // distinct per k-step.
    {
        const int wid  = tid >> 5;
        const int lane = tid & 31;
        const int psub = lane >> 3;        // 0..3
        const int cg   = lane & 7;         // 0..7 -> channels 4*cg..4*cg+3
        const float* t0 = tile + (4 * cg + 0) * TS;
        const float* t1 = tile + (4 * cg + 1) * TS;
        const float* t2 = tile + (4 * cg + 2) * TS;
        const float* t3 = tile + (4 * cg + 3) * TS;
        float* attb = out + OFF_ATT + (size_t)b * HW * CHAN + c0 + 4 * cg;
        // p0 takes values wid*4 + 32m; max generated p0 = 192 -> p <= 195, no guard needed
        for (int p0 = wid * 4; p0 < HW; p0 += 32) {
            const int p = p0 + psub;
            float4 v;
            v.x = t0[p];
            v.y = t1[p];
            v.z = t2[p];
            v.w = t3[p];
            *reinterpret_cast<float4*>(attb + (size_t)p * CHAN) = v;
        }
    }
    __syncthreads();

    // ---- Phase 3a: in-place y-prefix per (channel, x) column ----
    // Mapping: lane = channel (c = tid & 31), x warp-uniform (x = tid >> 5).
    // Banks = (5*c + 14*y + x) mod 32: 5*c covers all 32 banks -> CONFLICT-FREE
    // LDS and STS (vs. the old c=t/14 mapping which had 2-way conflicts).
    // Two passes: x = tid>>5 (0..7), then x = 8 + tid>>5 (warps 0..5).
    {
        const int c = tid & 31;
        float* tp = tile + c * TS;
        #pragma unroll
        for (int pass = 0; pass < 2; ++pass) {
            const int x = (tid >> 5) + pass * 8;
            if (x < PSZ) {
                float* col = tp + x;
                float s = col[0];
                #pragma unroll
                for (int y = 1; y < PSZ; ++y) {
                    s += col[y * PSZ];
                    col[y * PSZ] = s;
                }
            }
        }
    }
    __syncthreads();

    // ---- Phase 3b: bu box means + fc (task 36 == full-plane mean) ----
    // Warp-uniform r (t>>5), lanes = channels -> LDS stride 197 = conflict-free.
    for (int t = tid; t < 37 * 32; t += NTHREADS) {
        const int r = t >> 5;
        const int c = t & 31;
        const float* tp = tile + c * TS;
        if (r < NBOX) {
            const int x1 = bx1[r], x2 = bx2[r];
            const int y1 = by1[r], y2 = by2[r];
            const float* bot = tp + (y2 - 1) * PSZ;
            float s = 0.0f;
            if (y1 > 0) {
                const float* top = tp + (y1 - 1) * PSZ;
                for (int x = x1; x < x2; ++x) s += bot[x] - top[x];
            } else {
                for (int x = x1; x < x2; ++x) s += bot[x];
            }
            out[OFF_BU + ((size_t)b * NBOX + r) * CHAN + c0 + c] = s * binv[r];
        } else {
            // fc: total = sum of last prefix row
            const float* last = tp + (PSZ - 1) * PSZ;
            float s = 0.0f;
            #pragma unroll
            for (int x = 0; x < PSZ; ++x) s += last[x];
            out[(size_t)b * CHAN + c0 + c] = s * (1.0f / (float)HW);
        }
    }
}

extern "C" void kernel_launch(void* const* d_in, const int* in_sizes, int n_in,
                              void* d_out, int out_size)
{
    const float* images = (const float*)d_in[0];
    const float* boxes  = (const float*)d_in[1];
    float* out = (float*)d_out;

    dim3 grid(CHAN / CT, BATCH);   // (64, 128) = 8192 blocks
    fused_pool_transpose_kernel<<<grid, NTHREADS>>>(images, boxes, out);
}